// round 1
// baseline (speedup 1.0000x reference)
#include <cuda_runtime.h>
#include <cuda_bf16.h>

// ============================================================================
// CMPNEncoder functional-group embedding:
//   out[g,h] = init[g,h] + sum_{fg: mapping[fg]==g} sum_{s<8} padded[func2atom[fg,s]] @ W
// Linearity lets us reduce the 133-dim raw features FIRST (340 MB of traffic),
// then do one tiny [100,133]x[133,300] GEMM, instead of a 32-GFLOP GEMM plus a
// 768 MB gather of 300-wide rows.
// ============================================================================

#define NUM_FUNCS   100     // fixed by reference (NUM_FUNCS)
#define FD_MAX      160     // max feature dim supported by 5 regs/lane
#define NCHUNK      8       // fg-range chunks per group -> grid = 8 x 100 CTAs
#define NWARPS      8
#define BLOCK       (NWARPS * 32)

// Per-(group,col) partial accumulator. Re-zeroed on every launch (graph replay).
__device__ float g_scratch[NUM_FUNCS * FD_MAX];

__global__ void zero_scratch_k(int n) {
    int i = blockIdx.x * blockDim.x + threadIdx.x;
    if (i < n) g_scratch[i] = 0.0f;
}

// Grid: (NCHUNK, NUM_FUNCS). CTA (c, g) scans fg-range c for entries with
// mapping[fg]==g, register-accumulates their 133-dim atom features.
__global__ __launch_bounds__(BLOCK) void gather_accum_k(
    const float* __restrict__ f_atoms,
    const int*   __restrict__ func2atom,
    const int*   __restrict__ mapping,
    int n_fg, int max_fg, int fdim)
{
    const int g     = blockIdx.y;
    const int ch    = (n_fg + gridDim.x - 1) / gridDim.x;
    const int lo    = blockIdx.x * ch;
    const int hi    = min(n_fg, lo + ch);
    const int w     = threadIdx.x >> 5;
    const int lane  = threadIdx.x & 31;

    float acc[5] = {0.f, 0.f, 0.f, 0.f, 0.f};

    // Warp-parallel ballot scan: 32 fgs checked per coalesced mapping load.
    for (int base = lo + w * 32; base < hi; base += BLOCK) {
        int fg = base + lane;
        int m  = (fg < hi) ? __ldg(mapping + fg) : -1;
        unsigned mk = __ballot_sync(0xffffffffu, m == g);
        while (mk) {
            int bit = __ffs(mk) - 1;
            mk &= mk - 1;
            int fgm = base + bit;
            // 8 indices of this functional group, one 32B sector.
            int a = (lane < max_fg) ? __ldg(func2atom + (long long)fgm * max_fg + lane) : 0;
            #pragma unroll 8
            for (int s = 0; s < max_fg; s++) {
                int row = __shfl_sync(0xffffffffu, a, s);
                if (row > 0) {   // 0 == padding (zero row); i>0 == atom i-1
                    const float* p = f_atoms + (long long)(row - 1) * fdim;
                    #pragma unroll
                    for (int j = 0; j < 5; j++) {
                        int c = lane + 32 * j;
                        if (c < fdim) acc[j] += __ldg(p + c);
                    }
                }
            }
        }
    }

    // Cross-warp reduction in smem, then one spread-address REDG per column.
    __shared__ float red[NWARPS][FD_MAX];
    #pragma unroll
    for (int j = 0; j < 5; j++) {
        int c = lane + 32 * j;
        if (c < FD_MAX) red[w][c] = acc[j];
    }
    __syncthreads();
    for (int c = threadIdx.x; c < fdim; c += BLOCK) {
        float s = 0.f;
        #pragma unroll
        for (int ww = 0; ww < NWARPS; ww++) s += red[ww][c];
        atomicAdd(&g_scratch[g * fdim + c], s);
    }
}

// out[g,h] = init[g,h] + sum_k scratch[g,k] * W[k,h].  Grid: NUM_FUNCS blocks,
// blockDim = hidden (300). W reads coalesced across h; scratch row broadcast
// from smem. 4 MFLOP total — noise.
__global__ void finish_k(
    const float* __restrict__ W,
    const float* __restrict__ init,
    float*       __restrict__ out,
    int fdim, int hidden)
{
    int g = blockIdx.x;
    int h = threadIdx.x;
    __shared__ float s[FD_MAX];
    for (int c = h; c < fdim; c += blockDim.x) s[c] = g_scratch[g * fdim + c];
    __syncthreads();
    if (h < hidden) {
        float sum = init[g * hidden + h];
        #pragma unroll 7
        for (int k = 0; k < fdim; k++)
            sum = fmaf(s[k], W[k * hidden + h], sum);
        out[g * hidden + h] = sum;
    }
}

extern "C" void kernel_launch(void* const* d_in, const int* in_sizes, int n_in,
                              void* d_out, int out_size)
{
    const float* f_atoms   = (const float*)d_in[0];   // [n_atoms, fdim]
    const float* W         = (const float*)d_in[1];   // [fdim, hidden]
    const int*   func2atom = (const int*)  d_in[2];   // [n_fg, max_fg]
    const int*   mapping   = (const int*)  d_in[3];   // [n_fg]
    const float* init      = (const float*)d_in[4];   // [NUM_FUNCS, hidden]
    float*       out       = (float*)d_out;           // [NUM_FUNCS, hidden]

    const int hidden = in_sizes[4] / NUM_FUNCS;       // 300
    const int fdim   = in_sizes[1] / hidden;          // 133
    const int n_fg   = in_sizes[3];                   // 80000
    const int max_fg = in_sizes[2] / n_fg;            // 8

    const int nscratch = NUM_FUNCS * fdim;
    zero_scratch_k<<<(nscratch + 255) / 256, 256>>>(nscratch);

    dim3 grid(NCHUNK, NUM_FUNCS);
    gather_accum_k<<<grid, BLOCK>>>(f_atoms, func2atom, mapping, n_fg, max_fg, fdim);

    finish_k<<<NUM_FUNCS, hidden>>>(W, init, out, fdim, hidden);
}

// round 3
// speedup vs baseline: 1.4437x; 1.4437x over previous
#include <cuda_runtime.h>
#include <cuda_bf16.h>

// ============================================================================
// CMPNEncoder functional-group embedding.
//   out[g,h] = init[g,h] + ( Σ_{fg: map[fg]==g} Σ_{s} f_atoms[func2atom[fg,s]-1] ) @ W
// Linearity: reduce 133-dim raw features per group FIRST, tiny GEMM LAST.
//
// Pipeline (all graph-capturable, zero allocations):
//   1. zero_k       : zero per-group cursors + partial accumulators
//   2. scatter_k    : bucket fg indices into per-group compact lists
//                     (smem-aggregated counting scatter, ~4k global atomics)
//   3. gather_k<133>: per (group, chunk) CTA walks its compact list and
//                     register-accumulates 133-dim rows. No scan, no ballot —
//                     clean loop ptxas can pipeline (40 indep LDG per fg).
//   4. finish_k     : [100,133] x [133,300] mini-GEMM + init add.
// ============================================================================

#define NUM_FUNCS   100
#define FD_MAX      160     // 5 regs/lane ceiling
#define CAP         4096    // per-group list capacity (mean 800, sd ~28)
#define NCHUNK      8       // list chunks per group -> 800 gather CTAs
#define NWARPS      8
#define BLOCK       (NWARPS * 32)

__device__ int   g_cursor[NUM_FUNCS];            // per-group fill cursor / final count
__device__ int   g_lists [NUM_FUNCS * CAP];      // compact fg indices per group
__device__ float g_scratch[NUM_FUNCS * FD_MAX];  // per-group raw-feature sums

// ---------------------------------------------------------------------------
__global__ void zero_k(int nscratch) {
    int i = blockIdx.x * blockDim.x + threadIdx.x;
    if (i < nscratch) g_scratch[i] = 0.0f;
    if (i < NUM_FUNCS) g_cursor[i] = 0;
}

// ---------------------------------------------------------------------------
// Bucket fgs by group. Each CTA covers FG_PER_CTA fgs; counts ranks in smem,
// reserves a global base per group with ONE atomic per (CTA, group), then
// scatters. 80k fgs -> ~4k global atomics total.
#define FG_PER_TH   8
#define FG_PER_CTA  (BLOCK * FG_PER_TH)   // 2048

__global__ __launch_bounds__(BLOCK) void scatter_k(
    const int* __restrict__ mapping, int n_fg)
{
    __shared__ int scnt[NUM_FUNCS];
    __shared__ int sbase[NUM_FUNCS];
    const int tid = threadIdx.x;
    const int lo  = blockIdx.x * FG_PER_CTA;
    const int hi  = min(n_fg, lo + FG_PER_CTA);

    for (int i = tid; i < NUM_FUNCS; i += BLOCK) scnt[i] = 0;
    __syncthreads();

    int myg[FG_PER_TH], myrank[FG_PER_TH];
    #pragma unroll
    for (int t = 0; t < FG_PER_TH; t++) {
        int fg = lo + t * BLOCK + tid;          // coalesced mapping reads
        myg[t] = -1;
        if (fg < hi) {
            int g = __ldg(mapping + fg);
            myg[t] = g;
            myrank[t] = atomicAdd(&scnt[g], 1);
        }
    }
    __syncthreads();
    for (int g = tid; g < NUM_FUNCS; g += BLOCK)
        sbase[g] = scnt[g] ? atomicAdd(&g_cursor[g], scnt[g]) : 0;
    __syncthreads();
    #pragma unroll
    for (int t = 0; t < FG_PER_TH; t++) {
        if (myg[t] >= 0) {
            int pos = sbase[myg[t]] + myrank[t];
            if (pos < CAP)
                g_lists[myg[t] * CAP + pos] = lo + t * BLOCK + tid;
        }
    }
}

// ---------------------------------------------------------------------------
// Gather + register accumulate. Grid: (NCHUNK, NUM_FUNCS).
template<int FD>
__global__ __launch_bounds__(BLOCK) void gather_k(
    const float* __restrict__ f_atoms,
    const int*   __restrict__ func2atom,
    int max_fg)
{
    constexpr int NJ = (FD + 31) / 32;          // 5 for FD=133
    const int g    = blockIdx.y;
    const int w    = threadIdx.x >> 5;
    const int lane = threadIdx.x & 31;

    const int cnt = min(g_cursor[g], CAP);
    const int lo  = (int)((long long)blockIdx.x       * cnt / NCHUNK);
    const int hi  = (int)((long long)(blockIdx.x + 1) * cnt / NCHUNK);
    const int* list = g_lists + g * CAP;

    float acc[NJ];
    #pragma unroll
    for (int j = 0; j < NJ; j++) acc[j] = 0.0f;

    for (int i = lo + w; i < hi; i += NWARPS) {
        const int fg = __ldg(list + i);         // warp-uniform broadcast load
        int a = (lane < max_fg)
              ? __ldg(func2atom + (long long)fg * max_fg + lane) : 0;
        #pragma unroll 8
        for (int s = 0; s < max_fg; s++) {
            int row = __shfl_sync(0xffffffffu, a, s);
            if (row > 0) {                      // 0 == padding row
                const float* p = f_atoms + (long long)(row - 1) * FD;
                #pragma unroll
                for (int j = 0; j < NJ; j++) {
                    int c = lane + 32 * j;
                    if (c < FD) acc[j] += __ldg(p + c);
                }
            }
        }
    }

    // cross-warp smem reduce, then one spread REDG per column
    __shared__ float red[NWARPS][FD_MAX];
    #pragma unroll
    for (int j = 0; j < NJ; j++) {
        int c = lane + 32 * j;
        if (c < FD_MAX) red[w][c] = acc[j];
    }
    __syncthreads();
    for (int c = threadIdx.x; c < FD; c += BLOCK) {
        float s = 0.f;
        #pragma unroll
        for (int ww = 0; ww < NWARPS; ww++) s += red[ww][c];
        atomicAdd(&g_scratch[g * FD + c], s);
    }
}

// ---------------------------------------------------------------------------
__global__ void finish_k(
    const float* __restrict__ W,
    const float* __restrict__ init,
    float*       __restrict__ out,
    int fdim, int hidden)
{
    int g = blockIdx.x;
    int h = threadIdx.x;
    __shared__ float s[FD_MAX];
    for (int c = h; c < fdim; c += blockDim.x) s[c] = g_scratch[g * fdim + c];
    __syncthreads();
    if (h < hidden) {
        float sum = init[g * hidden + h];
        #pragma unroll 7
        for (int k = 0; k < fdim; k++)
            sum = fmaf(s[k], W[k * hidden + h], sum);
        out[g * hidden + h] = sum;
    }
}

// ---------------------------------------------------------------------------
extern "C" void kernel_launch(void* const* d_in, const int* in_sizes, int n_in,
                              void* d_out, int out_size)
{
    const float* f_atoms   = (const float*)d_in[0];
    const float* W         = (const float*)d_in[1];
    const int*   func2atom = (const int*)  d_in[2];
    const int*   mapping   = (const int*)  d_in[3];
    const float* init      = (const float*)d_in[4];
    float*       out       = (float*)d_out;

    const int hidden = in_sizes[4] / NUM_FUNCS;   // 300
    const int fdim   = in_sizes[1] / hidden;      // 133
    const int n_fg   = in_sizes[3];               // 80000
    const int max_fg = in_sizes[2] / n_fg;        // 8

    const int nscratch = NUM_FUNCS * fdim;
    zero_k<<<(max(nscratch, NUM_FUNCS) + 255) / 256, 256>>>(nscratch);

    scatter_k<<<(n_fg + FG_PER_CTA - 1) / FG_PER_CTA, BLOCK>>>(mapping, n_fg);

    dim3 grid(NCHUNK, NUM_FUNCS);
    if (fdim == 133) {
        gather_k<133><<<grid, BLOCK>>>(f_atoms, func2atom, max_fg);
        finish_k<<<NUM_FUNCS, hidden>>>(W, init, out, 133, hidden);
    } else {
        // generic fallback (fdim <= FD_MAX)
        gather_k<FD_MAX><<<grid, BLOCK>>>(f_atoms, func2atom, max_fg);
        finish_k<<<NUM_FUNCS, hidden>>>(W, init, out, fdim, hidden);
    }
}